// round 15
// baseline (speedup 1.0000x reference)
#include <cuda_runtime.h>
#include <cuda_fp16.h>
#include <math.h>
#include <stdint.h>

#define NN 8192
#define DD 512
#define EPSF 1e-8f

// ---------------- scratch (__device__ globals; no allocation) ----------------
__device__ float  g_Wh [(size_t)NN * DD];          // fp32 Wh
__device__ __half g_hh [(size_t)NN * DD];          // h splits
__device__ __half g_hl [(size_t)NN * DD];
__device__ __half g_wsh[(size_t)DD * DD];          // W splits
__device__ __half g_wsl[(size_t)DD * DD];
__device__ __half g_An [(size_t)NN * DD];          // normalized Wh (fp16)
__device__ __half g_Vt [(size_t)DD * NN];          // Wh^T (fp16)
__device__ __half g_p  [(size_t)NN * NN];          // p = exp(sim-1) masked (134MB)
__device__ float  g_inv[NN];                       // 1 / row sum

// ---------------- PTX helpers (baseline PTX, sm_80+) ------------------------
__device__ __forceinline__ uint32_t smem_u32(const void* p) {
    uint32_t a;
    asm("{ .reg .u64 t; cvta.to.shared.u64 t, %1; cvt.u32.u64 %0, t; }"
        : "=r"(a) : "l"(p));
    return a;
}
__device__ __forceinline__ void cpasync16(uint32_t dst, const void* src) {
    asm volatile("cp.async.cg.shared.global [%0], [%1], 16;"
                 :: "r"(dst), "l"(src) : "memory");
}
__device__ __forceinline__ void cp_commit() {
    asm volatile("cp.async.commit_group;" ::: "memory");
}
__device__ __forceinline__ void ldsm4(uint32_t* r, uint32_t addr) {
    asm volatile("ldmatrix.sync.aligned.m8n8.x4.shared.b16 {%0,%1,%2,%3}, [%4];"
                 : "=r"(r[0]), "=r"(r[1]), "=r"(r[2]), "=r"(r[3]) : "r"(addr));
}
__device__ __forceinline__ void mma16816h(float* d, const uint32_t* a, const uint32_t* b) {
    asm volatile(
        "mma.sync.aligned.m16n8k16.row.col.f32.f16.f16.f32 "
        "{%0,%1,%2,%3}, {%4,%5,%6,%7}, {%8,%9}, {%0,%1,%2,%3};"
        : "+f"(d[0]), "+f"(d[1]), "+f"(d[2]), "+f"(d[3])
        : "r"(a[0]), "r"(a[1]), "r"(a[2]), "r"(a[3]), "r"(b[0]), "r"(b[1]));
}

// swizzled offset in a [rows x 32 f16] tile (64B pitch, 16B units)
__device__ __forceinline__ uint32_t swz64(int row, int u) {
    return (uint32_t)(row * 64 + ((u ^ ((row >> 1) & 3)) << 4));
}
// swizzled offset in a [rows x 64 f16] tile (128B pitch, 16B units)
__device__ __forceinline__ uint32_t swz128(int row, int u) {
    return (uint32_t)(row * 128 + ((u ^ (row & 7)) << 4));
}

// ---------------------------------------------------------------------------
// split: x -> fp16 hi + fp16 lo
// ---------------------------------------------------------------------------
__global__ void split_hl(const float* __restrict__ x, __half* __restrict__ hi,
                         __half* __restrict__ lo, int n)
{
    int i = blockIdx.x * blockDim.x + threadIdx.x;
    if (i < n) {
        float v = x[i];
        __half h = __float2half_rn(v);
        hi[i] = h;
        lo[i] = __float2half_rn(v - __half2float(h));
    }
}

// ---------------------------------------------------------------------------
// 3-term fp16-split GEMM (NT): C = (Ahi+Alo)@(Bhi+Blo)^T -> fp32 C.
// CTA 128x128, K-chunk 32, 3-stage pipeline. (Wh = h @ W^T)
// ---------------------------------------------------------------------------
__global__ __launch_bounds__(256, 2)
void hmma3h(const __half* __restrict__ Ahi, const __half* __restrict__ Alo,
            const __half* __restrict__ Bhi, const __half* __restrict__ Blo,
            float* __restrict__ C, int K, int Cld)
{
    extern __shared__ char smem[];
    const uint32_t base = smem_u32(smem);

    const int tid  = threadIdx.x;
    const int lane = tid & 31;
    const int wid  = tid >> 5;
    const int warp_m = wid & 1;
    const int warp_n = wid >> 1;
    const int rowBase = blockIdx.y * 128;
    const int colBase = blockIdx.x * 128;

    const __half* srcs[4] = { Ahi, Alo, Bhi, Blo };
    const int rb[4] = { rowBase, rowBase, colBase, colBase };

    float acc[4][4][4];
#pragma unroll
    for (int mi = 0; mi < 4; mi++)
#pragma unroll
        for (int ni = 0; ni < 4; ni++)
#pragma unroll
            for (int r = 0; r < 4; r++) acc[mi][ni][r] = 0.f;

    const int NC = K >> 5;

    auto prefetch = [&](int c, int stage) {
#pragma unroll
        for (int it = 0; it < 8; it++) {
            const int t   = it >> 1;
            const int rem = ((it & 1) << 8) + tid;
            const int row = rem >> 2;
            const int u   = rem & 3;
            const __half* sp =
                srcs[t] + (size_t)(rb[t] + row) * K + ((size_t)c << 5) + u * 8;
            uint32_t dst = base + (uint32_t)stage * 32768u + (uint32_t)t * 8192u
                         + swz64(row, u);
            cpasync16(dst, sp);
        }
        cp_commit();
    };

    prefetch(0, 0);
    prefetch(1, 1);

    for (int c = 0; c < NC; c++) {
        if (c + 1 < NC) asm volatile("cp.async.wait_group 1;" ::: "memory");
        else            asm volatile("cp.async.wait_group 0;" ::: "memory");
        __syncthreads();
        if (c + 2 < NC) prefetch(c + 2, (c + 2) % 3);

        const uint32_t st   = base + (uint32_t)(c % 3) * 32768u;
        const uint32_t tAhi = st;
        const uint32_t tAlo = st + 8192u;
        const uint32_t tBhi = st + 16384u;
        const uint32_t tBlo = st + 24576u;
        const int lrow = lane & 15;

#pragma unroll
        for (int ks = 0; ks < 2; ks++) {
            const int lu = ks * 2 + (lane >> 4);
            uint32_t ah[4][4], bh[4][2], bl[4][2];
#pragma unroll
            for (int mi = 0; mi < 4; mi++)
                ldsm4(ah[mi], tAhi + swz64(warp_m * 64 + mi * 16 + lrow, lu));
#pragma unroll
            for (int g = 0; g < 2; g++) {
                uint32_t r[4];
                ldsm4(r, tBhi + swz64(warp_n * 32 + g * 16 + lrow, lu));
                bh[g * 2 + 0][0] = r[0]; bh[g * 2 + 1][0] = r[1];
                bh[g * 2 + 0][1] = r[2]; bh[g * 2 + 1][1] = r[3];
                ldsm4(r, tBlo + swz64(warp_n * 32 + g * 16 + lrow, lu));
                bl[g * 2 + 0][0] = r[0]; bl[g * 2 + 1][0] = r[1];
                bl[g * 2 + 0][1] = r[2]; bl[g * 2 + 1][1] = r[3];
            }
#pragma unroll
            for (int mi = 0; mi < 4; mi++)
#pragma unroll
                for (int ni = 0; ni < 4; ni++) {
                    mma16816h(acc[mi][ni], ah[mi], bh[ni]);
                    mma16816h(acc[mi][ni], ah[mi], bl[ni]);
                }
            uint32_t al[4][4];
#pragma unroll
            for (int mi = 0; mi < 4; mi++)
                ldsm4(al[mi], tAlo + swz64(warp_m * 64 + mi * 16 + lrow, lu));
#pragma unroll
            for (int mi = 0; mi < 4; mi++)
#pragma unroll
                for (int ni = 0; ni < 4; ni++)
                    mma16816h(acc[mi][ni], al[mi], bh[ni]);
        }
    }

    const int quad = lane >> 2;
    const int qt   = lane & 3;
#pragma unroll
    for (int mi = 0; mi < 4; mi++) {
#pragma unroll
        for (int ni = 0; ni < 4; ni++) {
            const int r0 = rowBase + warp_m * 64 + mi * 16 + quad;
            const int r1 = r0 + 8;
            const int cc = colBase + warp_n * 32 + ni * 8 + qt * 2;
            const float* a4 = acc[mi][ni];
            *reinterpret_cast<float2*>(C + (size_t)r0 * Cld + cc) =
                make_float2(a4[0], a4[1]);
            *reinterpret_cast<float2*>(C + (size_t)r1 * Cld + cc) =
                make_float2(a4[2], a4[3]);
        }
    }
}

// ---------------------------------------------------------------------------
// 64x64-warp-tile single-term fp16 GEMM (NT), 4 warps, CTA 128x128,
// K-chunk 64, 3-stage cp.async pipeline (32KB/stage), 2 CTAs/SM.
//   SIM=true : C is fp16 P, epilogue p = mask ? exp(sim-1) : 0
//   SIM=false: C is fp32, epilogue scales by inv[row]
// ---------------------------------------------------------------------------
template <bool SIM>
__global__ __launch_bounds__(128, 2)
void hmma_w64(const __half* __restrict__ A, const __half* __restrict__ B,
              void* __restrict__ Cout, int K, int Cld,
              const int* __restrict__ adj, const float* __restrict__ inv)
{
    extern __shared__ char smem[];
    const uint32_t base = smem_u32(smem);

    const int tid  = threadIdx.x;
    const int lane = tid & 31;
    const int wid  = tid >> 5;            // 0..3
    const int warp_m = wid & 1;           // 2 x 2 warp grid
    const int warp_n = wid >> 1;
    const int rowBase = blockIdx.y * 128;
    const int colBase = blockIdx.x * 128;

    float acc[4][8][4];
#pragma unroll
    for (int mi = 0; mi < 4; mi++)
#pragma unroll
        for (int ni = 0; ni < 8; ni++)
#pragma unroll
            for (int r = 0; r < 4; r++) acc[mi][ni][r] = 0.f;

    const int NC = K >> 6;

    // stage: A 128x64 f16 (16KB) @ +0, B 128x64 f16 @ +16KB; stride 32KB
    auto prefetch = [&](int c, int stage) {
#pragma unroll
        for (int it = 0; it < 16; it++) {
            const int t   = it >> 3;                    // 0 = A, 1 = B
            const int rem = ((it & 7) << 7) + tid;      // 0..1023
            const int row = rem >> 3;
            const int u   = rem & 7;
            const __half* sp = (t ? B + (size_t)(colBase + row) * K
                                  : A + (size_t)(rowBase + row) * K)
                             + ((size_t)c << 6) + u * 8;
            uint32_t dst = base + (uint32_t)stage * 32768u + (uint32_t)t * 16384u
                         + swz128(row, u);
            cpasync16(dst, sp);
        }
        cp_commit();
    };

    prefetch(0, 0);
    prefetch(1, 1);

    for (int c = 0; c < NC; c++) {
        if (c + 1 < NC) asm volatile("cp.async.wait_group 1;" ::: "memory");
        else            asm volatile("cp.async.wait_group 0;" ::: "memory");
        __syncthreads();
        if (c + 2 < NC) prefetch(c + 2, (c + 2) % 3);

        const uint32_t sA = base + (uint32_t)(c % 3) * 32768u;
        const uint32_t sB = sA + 16384u;
        const int lrow = lane & 15;
#pragma unroll
        for (int ks = 0; ks < 4; ks++) {
            const int lu = ks * 2 + (lane >> 4);
            uint32_t a[4][4], b[8][2];
#pragma unroll
            for (int mi = 0; mi < 4; mi++)
                ldsm4(a[mi], sA + swz128(warp_m * 64 + mi * 16 + lrow, lu));
#pragma unroll
            for (int g = 0; g < 4; g++) {
                uint32_t t4[4];
                ldsm4(t4, sB + swz128(warp_n * 64 + g * 16 + lrow, lu));
                b[g * 2 + 0][0] = t4[0]; b[g * 2 + 1][0] = t4[1];
                b[g * 2 + 0][1] = t4[2]; b[g * 2 + 1][1] = t4[3];
            }
#pragma unroll
            for (int mi = 0; mi < 4; mi++)
#pragma unroll
                for (int ni = 0; ni < 8; ni++)
                    mma16816h(acc[mi][ni], a[mi], b[ni]);
        }
    }

    // -------------------------- epilogue ---------------------------------
    const int quad = lane >> 2;
    const int qt   = lane & 3;
    if (SIM) {
        __half* P = (__half*)Cout;
#pragma unroll
        for (int mi = 0; mi < 4; mi++) {
            const int r0 = rowBase + warp_m * 64 + mi * 16 + quad;
            const int r1 = r0 + 8;
#pragma unroll
            for (int ni = 0; ni < 8; ni++) {
                const int cc = colBase + warp_n * 64 + ni * 8 + qt * 2;
                const float* a4 = acc[mi][ni];
                int2 m0 = *reinterpret_cast<const int2*>(adj + (size_t)r0 * NN + cc);
                int2 m1 = *reinterpret_cast<const int2*>(adj + (size_t)r1 * NN + cc);
                float p00 = (m0.x > 0 || r0 == cc)     ? __expf(a4[0] - 1.f) : 0.f;
                float p01 = (m0.y > 0 || r0 == cc + 1) ? __expf(a4[1] - 1.f) : 0.f;
                float p10 = (m1.x > 0 || r1 == cc)     ? __expf(a4[2] - 1.f) : 0.f;
                float p11 = (m1.y > 0 || r1 == cc + 1) ? __expf(a4[3] - 1.f) : 0.f;
                *reinterpret_cast<__half2*>(P + (size_t)r0 * (size_t)Cld + cc) =
                    __floats2half2_rn(p00, p01);
                *reinterpret_cast<__half2*>(P + (size_t)r1 * (size_t)Cld + cc) =
                    __floats2half2_rn(p10, p11);
            }
        }
    } else {
        float* C = (float*)Cout;
#pragma unroll
        for (int mi = 0; mi < 4; mi++) {
            const int r0 = rowBase + warp_m * 64 + mi * 16 + quad;
            const int r1 = r0 + 8;
            const float iv0 = inv[r0];
            const float iv1 = inv[r1];
#pragma unroll
            for (int ni = 0; ni < 8; ni++) {
                const int cc = colBase + warp_n * 64 + ni * 8 + qt * 2;
                const float* a4 = acc[mi][ni];
                *reinterpret_cast<float2*>(C + (size_t)r0 * Cld + cc) =
                    make_float2(a4[0] * iv0, a4[1] * iv0);
                *reinterpret_cast<float2*>(C + (size_t)r1 * Cld + cc) =
                    make_float2(a4[2] * iv1, a4[3] * iv1);
            }
        }
    }
}

// ---------------------------------------------------------------------------
// prep: per-row normalize Wh -> fp16. One warp per row.
// ---------------------------------------------------------------------------
__global__ void prep_norm_f16(const float* __restrict__ Wh, __half* __restrict__ A)
{
    int row  = blockIdx.x * 8 + (threadIdx.x >> 5);
    int lane = threadIdx.x & 31;
    const float4* r4 = reinterpret_cast<const float4*>(Wh + (size_t)row * DD);

    float4 v[4];
    float ss = 0.f;
#pragma unroll
    for (int i = 0; i < 4; i++) {
        v[i] = r4[lane + i * 32];
        ss = fmaf(v[i].x, v[i].x, ss); ss = fmaf(v[i].y, v[i].y, ss);
        ss = fmaf(v[i].z, v[i].z, ss); ss = fmaf(v[i].w, v[i].w, ss);
    }
#pragma unroll
    for (int off = 16; off > 0; off >>= 1) ss += __shfl_xor_sync(0xffffffffu, ss, off);
    float s = rsqrtf(ss + EPSF);

    __half* pa = A + (size_t)row * DD;
#pragma unroll
    for (int i = 0; i < 4; i++) {
        int col = (lane + i * 32) * 4;
        *reinterpret_cast<__half2*>(pa + col)     = __floats2half2_rn(v[i].x * s, v[i].y * s);
        *reinterpret_cast<__half2*>(pa + col + 2) = __floats2half2_rn(v[i].z * s, v[i].w * s);
    }
}

// ---------------------------------------------------------------------------
// transpose Wh -> fp16 V^T.
// ---------------------------------------------------------------------------
__global__ void t_f16(const float* __restrict__ Wh, __half* __restrict__ th)
{
    __shared__ float t[32][33];
    int bx = blockIdx.x, by = blockIdx.y;
    int tx = threadIdx.x, ty = threadIdx.y;
#pragma unroll
    for (int i = 0; i < 32; i += 8)
        t[ty + i][tx] = Wh[(size_t)(by * 32 + ty + i) * DD + bx * 32 + tx];
    __syncthreads();
#pragma unroll
    for (int i = 0; i < 32; i += 8) {
        size_t o = (size_t)(bx * 32 + ty + i) * NN + by * 32 + tx;
        th[o] = __float2half_rn(t[tx][ty + i]);
    }
}

// ---------------------------------------------------------------------------
// rowsum: inv[row] = 1 / sum(P[row, :])   (fp32 accumulate, uint4 loads)
// ---------------------------------------------------------------------------
__global__ void rowsum_inv(const __half* __restrict__ P, float* __restrict__ inv)
{
    __shared__ float red[256];
    const size_t row = blockIdx.x;
    const uint4* p4 = reinterpret_cast<const uint4*>(P + row * (size_t)NN);
    const int tid = threadIdx.x;

    float s = 0.f;
#pragma unroll
    for (int i = 0; i < NN / (8 * 256); i++) {
        uint4 v = p4[tid + i * 256];
        __half2 a = *reinterpret_cast<__half2*>(&v.x);
        __half2 b = *reinterpret_cast<__half2*>(&v.y);
        __half2 c = *reinterpret_cast<__half2*>(&v.z);
        __half2 d = *reinterpret_cast<__half2*>(&v.w);
        float2 fa = __half22float2(a), fb = __half22float2(b);
        float2 fc = __half22float2(c), fd = __half22float2(d);
        s += (fa.x + fa.y) + (fb.x + fb.y) + (fc.x + fc.y) + (fd.x + fd.y);
    }
    red[tid] = s; __syncthreads();
    for (int st = 128; st > 0; st >>= 1) {
        if (tid < st) red[tid] += red[tid + st];
        __syncthreads();
    }
    if (tid == 0) inv[row] = 1.0f / red[0];
}

// ---------------------------------------------------------------------------
extern "C" void kernel_launch(void* const* d_in, const int* in_sizes, int n_in,
                              void* d_out, int out_size)
{
    const float* h   = (const float*)d_in[0];   // [8192, 512]
    const int*   adj = (const int*)d_in[1];     // [8192, 8192]
    const float* W   = (const float*)d_in[2];   // [512, 512]
    float* out = (float*)d_out;                 // [8192, 512]

    void* p;
    cudaGetSymbolAddress(&p, g_Wh);  float*  Wh  = (float*)p;
    cudaGetSymbolAddress(&p, g_hh);  __half* hh  = (__half*)p;
    cudaGetSymbolAddress(&p, g_hl);  __half* hl  = (__half*)p;
    cudaGetSymbolAddress(&p, g_wsh); __half* wsh = (__half*)p;
    cudaGetSymbolAddress(&p, g_wsl); __half* wsl = (__half*)p;
    cudaGetSymbolAddress(&p, g_An);  __half* An  = (__half*)p;
    cudaGetSymbolAddress(&p, g_Vt);  __half* Vt  = (__half*)p;
    cudaGetSymbolAddress(&p, g_p);   __half* P   = (__half*)p;
    cudaGetSymbolAddress(&p, g_inv); float*  inv = (float*)p;

    const int SMEM = 98304;
    cudaFuncSetAttribute((const void*)hmma3h,
                         cudaFuncAttributeMaxDynamicSharedMemorySize, SMEM);
    cudaFuncSetAttribute((const void*)hmma_w64<true>,
                         cudaFuncAttributeMaxDynamicSharedMemorySize, SMEM);
    cudaFuncSetAttribute((const void*)hmma_w64<false>,
                         cudaFuncAttributeMaxDynamicSharedMemorySize, SMEM);

    // 1) fp16 splits of h and W
    split_hl<<<(NN * DD + 255) / 256, 256>>>(h, hh, hl, NN * DD);
    split_hl<<<(DD * DD + 255) / 256, 256>>>(W, wsh, wsl, DD * DD);
    // 2) Wh = h @ W^T via 3-term fp16 HMMA (fp32 out)
    hmma3h<<<dim3(DD / 128, NN / 128), 256, SMEM>>>(hh, hl, wsh, wsl, Wh, DD, DD);
    // 3) normalized rows -> fp16
    prep_norm_f16<<<NN / 8, 256>>>(Wh, An);
    // 4) Wh^T -> fp16 (V of AV GEMM)
    t_f16<<<dim3(DD / 32, NN / 32), dim3(32, 8)>>>(Wh, Vt);
    // 5) P = exp(sim - 1) masked  (64x64-warp single-term fp16 HMMA)
    hmma_w64<true><<<dim3(NN / 128, NN / 128), 128, SMEM>>>(
        An, An, (void*)P, DD, NN, adj, nullptr);
    // 6) inv row sums
    rowsum_inv<<<NN, 256>>>(P, inv);
    // 7) out = (P @ V^T) * inv  (64x64-warp single-term fp16 HMMA, K = 8192)
    hmma_w64<false><<<dim3(DD / 128, NN / 128), 128, SMEM>>>(
        P, Vt, (void*)out, NN, DD, nullptr, inv);
}

// round 16
// speedup vs baseline: 1.2392x; 1.2392x over previous
#include <cuda_runtime.h>
#include <cuda_fp16.h>
#include <math.h>
#include <stdint.h>

#define NN 8192
#define DD 512
#define EPSF 1e-8f

// ---------------- scratch (__device__ globals; no allocation) ----------------
__device__ float  g_Wh [(size_t)NN * DD];          // fp32 Wh
__device__ __half g_hh [(size_t)NN * DD];          // h splits
__device__ __half g_hl [(size_t)NN * DD];
__device__ __half g_wsh[(size_t)DD * DD];          // W splits
__device__ __half g_wsl[(size_t)DD * DD];
__device__ __half g_An [(size_t)NN * DD];          // normalized Wh (fp16)
__device__ __half g_Vt [(size_t)DD * NN];          // Wh^T (fp16)
__device__ __half g_p  [(size_t)NN * NN];          // p = exp(sim-1) masked (134MB)
__device__ float  g_part[(size_t)NN * 256];        // per-(row, 32-colblock) sums
__device__ float  g_inv[NN];                       // 1 / row sum

// ---------------- PTX helpers (baseline PTX, sm_80+) ------------------------
__device__ __forceinline__ uint32_t smem_u32(const void* p) {
    uint32_t a;
    asm("{ .reg .u64 t; cvta.to.shared.u64 t, %1; cvt.u32.u64 %0, t; }"
        : "=r"(a) : "l"(p));
    return a;
}
__device__ __forceinline__ void cpasync16(uint32_t dst, const void* src) {
    asm volatile("cp.async.cg.shared.global [%0], [%1], 16;"
                 :: "r"(dst), "l"(src) : "memory");
}
__device__ __forceinline__ void cp_commit() {
    asm volatile("cp.async.commit_group;" ::: "memory");
}
__device__ __forceinline__ void ldsm4(uint32_t* r, uint32_t addr) {
    asm volatile("ldmatrix.sync.aligned.m8n8.x4.shared.b16 {%0,%1,%2,%3}, [%4];"
                 : "=r"(r[0]), "=r"(r[1]), "=r"(r[2]), "=r"(r[3]) : "r"(addr));
}
__device__ __forceinline__ void mma16816h(float* d, const uint32_t* a, const uint32_t* b) {
    asm volatile(
        "mma.sync.aligned.m16n8k16.row.col.f32.f16.f16.f32 "
        "{%0,%1,%2,%3}, {%4,%5,%6,%7}, {%8,%9}, {%0,%1,%2,%3};"
        : "+f"(d[0]), "+f"(d[1]), "+f"(d[2]), "+f"(d[3])
        : "r"(a[0]), "r"(a[1]), "r"(a[2]), "r"(a[3]), "r"(b[0]), "r"(b[1]));
}

// swizzled offset in a [rows x 32 f16] tile (64B pitch, 16B units)
__device__ __forceinline__ uint32_t swz64(int row, int u) {
    return (uint32_t)(row * 64 + ((u ^ ((row >> 1) & 3)) << 4));
}
// swizzled offset in a [rows x 64 f16] tile (128B pitch, 16B units)
__device__ __forceinline__ uint32_t swz128(int row, int u) {
    return (uint32_t)(row * 128 + ((u ^ (row & 7)) << 4));
}

// ---------------------------------------------------------------------------
// split: x -> fp16 hi + fp16 lo
// ---------------------------------------------------------------------------
__global__ void split_hl(const float* __restrict__ x, __half* __restrict__ hi,
                         __half* __restrict__ lo, int n)
{
    int i = blockIdx.x * blockDim.x + threadIdx.x;
    if (i < n) {
        float v = x[i];
        __half h = __float2half_rn(v);
        hi[i] = h;
        lo[i] = __float2half_rn(v - __half2float(h));
    }
}

// ---------------------------------------------------------------------------
// 3-term fp16-split GEMM (NT): C = (Ahi+Alo)@(Bhi+Blo)^T -> fp32 C.
// CTA 128x128, K-chunk 32, 3-stage pipeline. (Wh = h @ W^T)
// ---------------------------------------------------------------------------
__global__ __launch_bounds__(256, 2)
void hmma3h(const __half* __restrict__ Ahi, const __half* __restrict__ Alo,
            const __half* __restrict__ Bhi, const __half* __restrict__ Blo,
            float* __restrict__ C, int K, int Cld)
{
    extern __shared__ char smem[];
    const uint32_t base = smem_u32(smem);

    const int tid  = threadIdx.x;
    const int lane = tid & 31;
    const int wid  = tid >> 5;
    const int warp_m = wid & 1;
    const int warp_n = wid >> 1;
    const int rowBase = blockIdx.y * 128;
    const int colBase = blockIdx.x * 128;

    const __half* srcs[4] = { Ahi, Alo, Bhi, Blo };
    const int rb[4] = { rowBase, rowBase, colBase, colBase };

    float acc[4][4][4];
#pragma unroll
    for (int mi = 0; mi < 4; mi++)
#pragma unroll
        for (int ni = 0; ni < 4; ni++)
#pragma unroll
            for (int r = 0; r < 4; r++) acc[mi][ni][r] = 0.f;

    const int NC = K >> 5;

    auto prefetch = [&](int c, int stage) {
#pragma unroll
        for (int it = 0; it < 8; it++) {
            const int t   = it >> 1;
            const int rem = ((it & 1) << 8) + tid;
            const int row = rem >> 2;
            const int u   = rem & 3;
            const __half* sp =
                srcs[t] + (size_t)(rb[t] + row) * K + ((size_t)c << 5) + u * 8;
            uint32_t dst = base + (uint32_t)stage * 32768u + (uint32_t)t * 8192u
                         + swz64(row, u);
            cpasync16(dst, sp);
        }
        cp_commit();
    };

    prefetch(0, 0);
    prefetch(1, 1);

    for (int c = 0; c < NC; c++) {
        if (c + 1 < NC) asm volatile("cp.async.wait_group 1;" ::: "memory");
        else            asm volatile("cp.async.wait_group 0;" ::: "memory");
        __syncthreads();
        if (c + 2 < NC) prefetch(c + 2, (c + 2) % 3);

        const uint32_t st   = base + (uint32_t)(c % 3) * 32768u;
        const uint32_t tAhi = st;
        const uint32_t tAlo = st + 8192u;
        const uint32_t tBhi = st + 16384u;
        const uint32_t tBlo = st + 24576u;
        const int lrow = lane & 15;

#pragma unroll
        for (int ks = 0; ks < 2; ks++) {
            const int lu = ks * 2 + (lane >> 4);
            uint32_t ah[4][4], bh[4][2], bl[4][2];
#pragma unroll
            for (int mi = 0; mi < 4; mi++)
                ldsm4(ah[mi], tAhi + swz64(warp_m * 64 + mi * 16 + lrow, lu));
#pragma unroll
            for (int g = 0; g < 2; g++) {
                uint32_t r[4];
                ldsm4(r, tBhi + swz64(warp_n * 32 + g * 16 + lrow, lu));
                bh[g * 2 + 0][0] = r[0]; bh[g * 2 + 1][0] = r[1];
                bh[g * 2 + 0][1] = r[2]; bh[g * 2 + 1][1] = r[3];
                ldsm4(r, tBlo + swz64(warp_n * 32 + g * 16 + lrow, lu));
                bl[g * 2 + 0][0] = r[0]; bl[g * 2 + 1][0] = r[1];
                bl[g * 2 + 0][1] = r[2]; bl[g * 2 + 1][1] = r[3];
            }
#pragma unroll
            for (int mi = 0; mi < 4; mi++)
#pragma unroll
                for (int ni = 0; ni < 4; ni++) {
                    mma16816h(acc[mi][ni], ah[mi], bh[ni]);
                    mma16816h(acc[mi][ni], ah[mi], bl[ni]);
                }
            uint32_t al[4][4];
#pragma unroll
            for (int mi = 0; mi < 4; mi++)
                ldsm4(al[mi], tAlo + swz64(warp_m * 64 + mi * 16 + lrow, lu));
#pragma unroll
            for (int mi = 0; mi < 4; mi++)
#pragma unroll
                for (int ni = 0; ni < 4; ni++)
                    mma16816h(acc[mi][ni], al[mi], bh[ni]);
        }
    }

    const int quad = lane >> 2;
    const int qt   = lane & 3;
#pragma unroll
    for (int mi = 0; mi < 4; mi++) {
#pragma unroll
        for (int ni = 0; ni < 4; ni++) {
            const int r0 = rowBase + warp_m * 64 + mi * 16 + quad;
            const int r1 = r0 + 8;
            const int cc = colBase + warp_n * 32 + ni * 8 + qt * 2;
            const float* a4 = acc[mi][ni];
            *reinterpret_cast<float2*>(C + (size_t)r0 * Cld + cc) =
                make_float2(a4[0], a4[1]);
            *reinterpret_cast<float2*>(C + (size_t)r1 * Cld + cc) =
                make_float2(a4[2], a4[3]);
        }
    }
}

// ---------------------------------------------------------------------------
// SIM GEMM (R12 shape): sim = An @ An^T, single fp16 term, 8 warps,
// CTA 128x128, K-chunk 64, 3-stage pipeline. Epilogue:
//   p = mask ? exp(sim-1) : 0 -> fp16 P; plus per-(row,32-colblock) partial
//   sums of the fp16-rounded p into `part` (fused rowsum).
// ---------------------------------------------------------------------------
__global__ __launch_bounds__(256, 2)
void hmma_sim(const __half* __restrict__ A, __half* __restrict__ P,
              int K, const int* __restrict__ adj, float* __restrict__ part)
{
    extern __shared__ char smem[];
    const uint32_t base = smem_u32(smem);

    const int tid  = threadIdx.x;
    const int lane = tid & 31;
    const int wid  = tid >> 5;
    const int warp_m = wid & 1;
    const int warp_n = wid >> 1;
    const int rowBase = blockIdx.y * 128;
    const int colBase = blockIdx.x * 128;

    // L2-prefetch this CTA's adjacency tile (128 rows x 512 bytes)
    {
        const char* ab = reinterpret_cast<const char*>(adj)
                       + (size_t)rowBase * NN * 4 + (size_t)colBase * 4;
#pragma unroll
        for (int i = 0; i < 2; i++) {
            int idx = tid + i * 256;              // 0..511
            int r = idx >> 2, seg = idx & 3;
            asm volatile("prefetch.global.L2 [%0];"
                         :: "l"(ab + (size_t)r * NN * 4 + seg * 128));
        }
    }

    float acc[4][4][4];
#pragma unroll
    for (int mi = 0; mi < 4; mi++)
#pragma unroll
        for (int ni = 0; ni < 4; ni++)
#pragma unroll
            for (int r = 0; r < 4; r++) acc[mi][ni][r] = 0.f;

    const int NC = K >> 6;

    auto prefetch = [&](int c, int stage) {
#pragma unroll
        for (int it = 0; it < 8; it++) {
            const int t   = it >> 2;
            const int rem = ((it & 3) << 8) + tid;
            const int row = rem >> 3;
            const int u   = rem & 7;
            const __half* sp = A + (size_t)((t ? colBase : rowBase) + row) * K
                             + ((size_t)c << 6) + u * 8;
            uint32_t dst = base + (uint32_t)stage * 32768u + (uint32_t)t * 16384u
                         + swz128(row, u);
            cpasync16(dst, sp);
        }
        cp_commit();
    };

    prefetch(0, 0);
    prefetch(1, 1);

    for (int c = 0; c < NC; c++) {
        if (c + 1 < NC) asm volatile("cp.async.wait_group 1;" ::: "memory");
        else            asm volatile("cp.async.wait_group 0;" ::: "memory");
        __syncthreads();
        if (c + 2 < NC) prefetch(c + 2, (c + 2) % 3);

        const uint32_t sA = base + (uint32_t)(c % 3) * 32768u;
        const uint32_t sB = sA + 16384u;
        const int lrow = lane & 15;
#pragma unroll
        for (int ks = 0; ks < 4; ks++) {
            const int lu = ks * 2 + (lane >> 4);
            uint32_t ah[4][4], b[4][2];
#pragma unroll
            for (int mi = 0; mi < 4; mi++)
                ldsm4(ah[mi], sA + swz128(warp_m * 64 + mi * 16 + lrow, lu));
#pragma unroll
            for (int g = 0; g < 2; g++) {
                uint32_t t4[4];
                ldsm4(t4, sB + swz128(warp_n * 32 + g * 16 + lrow, lu));
                b[g * 2 + 0][0] = t4[0]; b[g * 2 + 1][0] = t4[1];
                b[g * 2 + 0][1] = t4[2]; b[g * 2 + 1][1] = t4[3];
            }
#pragma unroll
            for (int mi = 0; mi < 4; mi++)
#pragma unroll
                for (int ni = 0; ni < 4; ni++)
                    mma16816h(acc[mi][ni], ah[mi], b[ni]);
        }
    }

    // epilogue: mask + exp(sim-1) -> fp16 P, plus fused partial row sums
    const int quad = lane >> 2;
    const int qt   = lane & 3;
    const int colblock = blockIdx.x * 4 + warp_n;   // global 32-col block index
#pragma unroll
    for (int mi = 0; mi < 4; mi++) {
        const int r0 = rowBase + warp_m * 64 + mi * 16 + quad;
        const int r1 = r0 + 8;
        float rs0 = 0.f, rs1 = 0.f;
#pragma unroll
        for (int ni = 0; ni < 4; ni++) {
            const int cc = colBase + warp_n * 32 + ni * 8 + qt * 2;
            const float* a4 = acc[mi][ni];
            int2 m0 = *reinterpret_cast<const int2*>(adj + (size_t)r0 * NN + cc);
            int2 m1 = *reinterpret_cast<const int2*>(adj + (size_t)r1 * NN + cc);
            float p00 = (m0.x > 0 || r0 == cc)     ? __expf(a4[0] - 1.f) : 0.f;
            float p01 = (m0.y > 0 || r0 == cc + 1) ? __expf(a4[1] - 1.f) : 0.f;
            float p10 = (m1.x > 0 || r1 == cc)     ? __expf(a4[2] - 1.f) : 0.f;
            float p11 = (m1.y > 0 || r1 == cc + 1) ? __expf(a4[3] - 1.f) : 0.f;
            __half2 h0 = __floats2half2_rn(p00, p01);
            __half2 h1 = __floats2half2_rn(p10, p11);
            *reinterpret_cast<__half2*>(P + (size_t)r0 * NN + cc) = h0;
            *reinterpret_cast<__half2*>(P + (size_t)r1 * NN + cc) = h1;
            // accumulate the fp16-ROUNDED values for exact consistency
            float2 f0 = __half22float2(h0);
            float2 f1 = __half22float2(h1);
            rs0 += f0.x + f0.y;
            rs1 += f1.x + f1.y;
        }
        // reduce across the 4 qt-lanes (same quad)
        rs0 += __shfl_xor_sync(0xffffffffu, rs0, 1);
        rs0 += __shfl_xor_sync(0xffffffffu, rs0, 2);
        rs1 += __shfl_xor_sync(0xffffffffu, rs1, 1);
        rs1 += __shfl_xor_sync(0xffffffffu, rs1, 2);
        if (qt == 0) {
            part[(size_t)r0 * 256 + colblock] = rs0;
            part[(size_t)r1 * 256 + colblock] = rs1;
        }
    }
}

// ---------------------------------------------------------------------------
// part_inv: inv[row] = 1 / sum over 256 partials. One warp per row.
// ---------------------------------------------------------------------------
__global__ void part_inv(const float* __restrict__ part, float* __restrict__ inv)
{
    int row  = blockIdx.x * 8 + (threadIdx.x >> 5);
    int lane = threadIdx.x & 31;
    const float4* p4 = reinterpret_cast<const float4*>(part + (size_t)row * 256);
    float s = 0.f;
#pragma unroll
    for (int i = 0; i < 2; i++) {
        float4 v = p4[lane + i * 32];
        s += (v.x + v.y) + (v.z + v.w);
    }
#pragma unroll
    for (int off = 16; off > 0; off >>= 1)
        s += __shfl_xor_sync(0xffffffffu, s, off);
    if (lane == 0) inv[row] = 1.0f / s;
}

// ---------------------------------------------------------------------------
// AV GEMM (R12 shape): out = (P @ V^T) * inv[row]. Single fp16 term, 8 warps,
// CTA 128x128, K-chunk 64, 3-stage pipeline.
// ---------------------------------------------------------------------------
__global__ __launch_bounds__(256, 2)
void hmma_av(const __half* __restrict__ P, const __half* __restrict__ V,
             float* __restrict__ C, int K, int Cld, const float* __restrict__ inv)
{
    extern __shared__ char smem[];
    const uint32_t base = smem_u32(smem);

    const int tid  = threadIdx.x;
    const int lane = tid & 31;
    const int wid  = tid >> 5;
    const int warp_m = wid & 1;
    const int warp_n = wid >> 1;
    const int rowBase = blockIdx.y * 128;
    const int colBase = blockIdx.x * 128;

    float acc[4][4][4];
#pragma unroll
    for (int mi = 0; mi < 4; mi++)
#pragma unroll
        for (int ni = 0; ni < 4; ni++)
#pragma unroll
            for (int r = 0; r < 4; r++) acc[mi][ni][r] = 0.f;

    const int NC = K >> 6;

    auto prefetch = [&](int c, int stage) {
#pragma unroll
        for (int it = 0; it < 8; it++) {
            const int t   = it >> 2;                    // 0 = P, 1 = V
            const int rem = ((it & 3) << 8) + tid;
            const int row = rem >> 3;
            const int u   = rem & 7;
            const __half* sp = (t ? V + (size_t)(colBase + row) * K
                                  : P + (size_t)(rowBase + row) * K)
                             + ((size_t)c << 6) + u * 8;
            uint32_t dst = base + (uint32_t)stage * 32768u + (uint32_t)t * 16384u
                         + swz128(row, u);
            cpasync16(dst, sp);
        }
        cp_commit();
    };

    prefetch(0, 0);
    prefetch(1, 1);

    for (int c = 0; c < NC; c++) {
        if (c + 1 < NC) asm volatile("cp.async.wait_group 1;" ::: "memory");
        else            asm volatile("cp.async.wait_group 0;" ::: "memory");
        __syncthreads();
        if (c + 2 < NC) prefetch(c + 2, (c + 2) % 3);

        const uint32_t sP = base + (uint32_t)(c % 3) * 32768u;
        const uint32_t sV = sP + 16384u;
        const int lrow = lane & 15;
#pragma unroll
        for (int ks = 0; ks < 4; ks++) {
            const int lu = ks * 2 + (lane >> 4);
            uint32_t ap[4][4], b[4][2];
#pragma unroll
            for (int mi = 0; mi < 4; mi++)
                ldsm4(ap[mi], sP + swz128(warp_m * 64 + mi * 16 + lrow, lu));
#pragma unroll
            for (int g = 0; g < 2; g++) {
                uint32_t t4[4];
                ldsm4(t4, sV + swz128(warp_n * 32 + g * 16 + lrow, lu));
                b[g * 2 + 0][0] = t4[0]; b[g * 2 + 1][0] = t4[1];
                b[g * 2 + 0][1] = t4[2]; b[g * 2 + 1][1] = t4[3];
            }
#pragma unroll
            for (int mi = 0; mi < 4; mi++)
#pragma unroll
                for (int ni = 0; ni < 4; ni++)
                    mma16816h(acc[mi][ni], ap[mi], b[ni]);
        }
    }

    const int quad = lane >> 2;
    const int qt   = lane & 3;
#pragma unroll
    for (int mi = 0; mi < 4; mi++) {
        const int r0 = rowBase + warp_m * 64 + mi * 16 + quad;
        const int r1 = r0 + 8;
        const float iv0 = inv[r0];
        const float iv1 = inv[r1];
#pragma unroll
        for (int ni = 0; ni < 4; ni++) {
            const int cc = colBase + warp_n * 32 + ni * 8 + qt * 2;
            const float* a4 = acc[mi][ni];
            *reinterpret_cast<float2*>(C + (size_t)r0 * Cld + cc) =
                make_float2(a4[0] * iv0, a4[1] * iv0);
            *reinterpret_cast<float2*>(C + (size_t)r1 * Cld + cc) =
                make_float2(a4[2] * iv1, a4[3] * iv1);
        }
    }
}

// ---------------------------------------------------------------------------
// prep: per-row normalize Wh -> fp16. One warp per row.
// ---------------------------------------------------------------------------
__global__ void prep_norm_f16(const float* __restrict__ Wh, __half* __restrict__ A)
{
    int row  = blockIdx.x * 8 + (threadIdx.x >> 5);
    int lane = threadIdx.x & 31;
    const float4* r4 = reinterpret_cast<const float4*>(Wh + (size_t)row * DD);

    float4 v[4];
    float ss = 0.f;
#pragma unroll
    for (int i = 0; i < 4; i++) {
        v[i] = r4[lane + i * 32];
        ss = fmaf(v[i].x, v[i].x, ss); ss = fmaf(v[i].y, v[i].y, ss);
        ss = fmaf(v[i].z, v[i].z, ss); ss = fmaf(v[i].w, v[i].w, ss);
    }
#pragma unroll
    for (int off = 16; off > 0; off >>= 1) ss += __shfl_xor_sync(0xffffffffu, ss, off);
    float s = rsqrtf(ss + EPSF);

    __half* pa = A + (size_t)row * DD;
#pragma unroll
    for (int i = 0; i < 4; i++) {
        int col = (lane + i * 32) * 4;
        *reinterpret_cast<__half2*>(pa + col)     = __floats2half2_rn(v[i].x * s, v[i].y * s);
        *reinterpret_cast<__half2*>(pa + col + 2) = __floats2half2_rn(v[i].z * s, v[i].w * s);
    }
}

// ---------------------------------------------------------------------------
// transpose Wh -> fp16 V^T.
// ---------------------------------------------------------------------------
__global__ void t_f16(const float* __restrict__ Wh, __half* __restrict__ th)
{
    __shared__ float t[32][33];
    int bx = blockIdx.x, by = blockIdx.y;
    int tx = threadIdx.x, ty = threadIdx.y;
#pragma unroll
    for (int i = 0; i < 32; i += 8)
        t[ty + i][tx] = Wh[(size_t)(by * 32 + ty + i) * DD + bx * 32 + tx];
    __syncthreads();
#pragma unroll
    for (int i = 0; i < 32; i += 8) {
        size_t o = (size_t)(bx * 32 + ty + i) * NN + by * 32 + tx;
        th[o] = __float2half_rn(t[tx][ty + i]);
    }
}

// ---------------------------------------------------------------------------
extern "C" void kernel_launch(void* const* d_in, const int* in_sizes, int n_in,
                              void* d_out, int out_size)
{
    const float* h   = (const float*)d_in[0];   // [8192, 512]
    const int*   adj = (const int*)d_in[1];     // [8192, 8192]
    const float* W   = (const float*)d_in[2];   // [512, 512]
    float* out = (float*)d_out;                 // [8192, 512]

    void* p;
    cudaGetSymbolAddress(&p, g_Wh);   float*  Wh  = (float*)p;
    cudaGetSymbolAddress(&p, g_hh);   __half* hh  = (__half*)p;
    cudaGetSymbolAddress(&p, g_hl);   __half* hl  = (__half*)p;
    cudaGetSymbolAddress(&p, g_wsh);  __half* wsh = (__half*)p;
    cudaGetSymbolAddress(&p, g_wsl);  __half* wsl = (__half*)p;
    cudaGetSymbolAddress(&p, g_An);   __half* An  = (__half*)p;
    cudaGetSymbolAddress(&p, g_Vt);   __half* Vt  = (__half*)p;
    cudaGetSymbolAddress(&p, g_p);    __half* P   = (__half*)p;
    cudaGetSymbolAddress(&p, g_part); float*  part= (float*)p;
    cudaGetSymbolAddress(&p, g_inv);  float*  inv = (float*)p;

    const int SMEM = 98304;
    cudaFuncSetAttribute((const void*)hmma3h,
                         cudaFuncAttributeMaxDynamicSharedMemorySize, SMEM);
    cudaFuncSetAttribute((const void*)hmma_sim,
                         cudaFuncAttributeMaxDynamicSharedMemorySize, SMEM);
    cudaFuncSetAttribute((const void*)hmma_av,
                         cudaFuncAttributeMaxDynamicSharedMemorySize, SMEM);

    // 1) fp16 splits of h and W
    split_hl<<<(NN * DD + 255) / 256, 256>>>(h, hh, hl, NN * DD);
    split_hl<<<(DD * DD + 255) / 256, 256>>>(W, wsh, wsl, DD * DD);
    // 2) Wh = h @ W^T via 3-term fp16 HMMA (fp32 out)
    hmma3h<<<dim3(DD / 128, NN / 128), 256, SMEM>>>(hh, hl, wsh, wsl, Wh, DD, DD);
    // 3) normalized rows -> fp16
    prep_norm_f16<<<NN / 8, 256>>>(Wh, An);
    // 4) Wh^T -> fp16 (V of AV GEMM)
    t_f16<<<dim3(DD / 32, NN / 32), dim3(32, 8)>>>(Wh, Vt);
    // 5) P = exp(sim - 1) masked + fused partial row sums
    hmma_sim<<<dim3(NN / 128, NN / 128), 256, SMEM>>>(An, P, DD, adj, part);
    // 6) reduce partials -> inv
    part_inv<<<NN / 8, 256>>>(part, inv);
    // 7) out = (P @ V^T) * inv  (single-term fp16 HMMA, K = 8192)
    hmma_av<<<dim3(DD / 128, NN / 128), 256, SMEM>>>(P, Vt, out, NN, DD, inv);
}

// round 17
// speedup vs baseline: 1.3550x; 1.0935x over previous
#include <cuda_runtime.h>
#include <cuda_fp16.h>
#include <math.h>
#include <stdint.h>

#define NN 8192
#define DD 512
#define EPSF 1e-8f

// ---------------- scratch (__device__ globals; no allocation) ----------------
__device__ float  g_Wh [(size_t)NN * DD];          // fp32 Wh
__device__ __half g_hh [(size_t)NN * DD];          // h splits
__device__ __half g_hl [(size_t)NN * DD];
__device__ __half g_wsh[(size_t)DD * DD];          // W splits
__device__ __half g_wsl[(size_t)DD * DD];
__device__ __half g_An [(size_t)NN * DD];          // normalized Wh (fp16)
__device__ __half g_Vt [(size_t)DD * NN];          // Wh^T (fp16)
__device__ __half g_p  [(size_t)NN * NN];          // p = exp(sim-1) masked (134MB)
__device__ float  g_part[(size_t)NN * 256];        // per-(row, 32-colblock) sums
__device__ float  g_inv[NN];                       // 1 / row sum

// ---------------- PTX helpers (baseline PTX, sm_80+) ------------------------
__device__ __forceinline__ uint32_t smem_u32(const void* p) {
    uint32_t a;
    asm("{ .reg .u64 t; cvta.to.shared.u64 t, %1; cvt.u32.u64 %0, t; }"
        : "=r"(a) : "l"(p));
    return a;
}
__device__ __forceinline__ void cpasync16(uint32_t dst, const void* src) {
    asm volatile("cp.async.cg.shared.global [%0], [%1], 16;"
                 :: "r"(dst), "l"(src) : "memory");
}
__device__ __forceinline__ void cp_commit() {
    asm volatile("cp.async.commit_group;" ::: "memory");
}
__device__ __forceinline__ void ldsm4(uint32_t* r, uint32_t addr) {
    asm volatile("ldmatrix.sync.aligned.m8n8.x4.shared.b16 {%0,%1,%2,%3}, [%4];"
                 : "=r"(r[0]), "=r"(r[1]), "=r"(r[2]), "=r"(r[3]) : "r"(addr));
}
__device__ __forceinline__ void mma16816h(float* d, const uint32_t* a, const uint32_t* b) {
    asm volatile(
        "mma.sync.aligned.m16n8k16.row.col.f32.f16.f16.f32 "
        "{%0,%1,%2,%3}, {%4,%5,%6,%7}, {%8,%9}, {%0,%1,%2,%3};"
        : "+f"(d[0]), "+f"(d[1]), "+f"(d[2]), "+f"(d[3])
        : "r"(a[0]), "r"(a[1]), "r"(a[2]), "r"(a[3]), "r"(b[0]), "r"(b[1]));
}

// swizzled offset in a [rows x 32 f16] tile (64B pitch, 16B units)
__device__ __forceinline__ uint32_t swz64(int row, int u) {
    return (uint32_t)(row * 64 + ((u ^ ((row >> 1) & 3)) << 4));
}
// swizzled offset in a [rows x 64 f16] tile (128B pitch, 16B units)
__device__ __forceinline__ uint32_t swz128(int row, int u) {
    return (uint32_t)(row * 128 + ((u ^ (row & 7)) << 4));
}

// ---------------------------------------------------------------------------
// split: x -> fp16 hi + fp16 lo
// ---------------------------------------------------------------------------
__global__ void split_hl(const float* __restrict__ x, __half* __restrict__ hi,
                         __half* __restrict__ lo, int n)
{
    int i = blockIdx.x * blockDim.x + threadIdx.x;
    if (i < n) {
        float v = x[i];
        __half h = __float2half_rn(v);
        hi[i] = h;
        lo[i] = __float2half_rn(v - __half2float(h));
    }
}

// ---------------------------------------------------------------------------
// 3-term fp16-split GEMM (NT): C = (Ahi+Alo)@(Bhi+Blo)^T -> fp32 C.
// CTA 128x128, K-chunk 32, 3-stage pipeline. (Wh = h @ W^T)
// ---------------------------------------------------------------------------
__global__ __launch_bounds__(256, 2)
void hmma3h(const __half* __restrict__ Ahi, const __half* __restrict__ Alo,
            const __half* __restrict__ Bhi, const __half* __restrict__ Blo,
            float* __restrict__ C, int K, int Cld)
{
    extern __shared__ char smem[];
    const uint32_t base = smem_u32(smem);

    const int tid  = threadIdx.x;
    const int lane = tid & 31;
    const int wid  = tid >> 5;
    const int warp_m = wid & 1;
    const int warp_n = wid >> 1;
    const int rowBase = blockIdx.y * 128;
    const int colBase = blockIdx.x * 128;

    const __half* srcs[4] = { Ahi, Alo, Bhi, Blo };
    const int rb[4] = { rowBase, rowBase, colBase, colBase };

    float acc[4][4][4];
#pragma unroll
    for (int mi = 0; mi < 4; mi++)
#pragma unroll
        for (int ni = 0; ni < 4; ni++)
#pragma unroll
            for (int r = 0; r < 4; r++) acc[mi][ni][r] = 0.f;

    const int NC = K >> 5;

    auto prefetch = [&](int c, int stage) {
#pragma unroll
        for (int it = 0; it < 8; it++) {
            const int t   = it >> 1;
            const int rem = ((it & 1) << 8) + tid;
            const int row = rem >> 2;
            const int u   = rem & 3;
            const __half* sp =
                srcs[t] + (size_t)(rb[t] + row) * K + ((size_t)c << 5) + u * 8;
            uint32_t dst = base + (uint32_t)stage * 32768u + (uint32_t)t * 8192u
                         + swz64(row, u);
            cpasync16(dst, sp);
        }
        cp_commit();
    };

    prefetch(0, 0);
    prefetch(1, 1);

    for (int c = 0; c < NC; c++) {
        if (c + 1 < NC) asm volatile("cp.async.wait_group 1;" ::: "memory");
        else            asm volatile("cp.async.wait_group 0;" ::: "memory");
        __syncthreads();
        if (c + 2 < NC) prefetch(c + 2, (c + 2) % 3);

        const uint32_t st   = base + (uint32_t)(c % 3) * 32768u;
        const uint32_t tAhi = st;
        const uint32_t tAlo = st + 8192u;
        const uint32_t tBhi = st + 16384u;
        const uint32_t tBlo = st + 24576u;
        const int lrow = lane & 15;

#pragma unroll
        for (int ks = 0; ks < 2; ks++) {
            const int lu = ks * 2 + (lane >> 4);
            uint32_t ah[4][4], bh[4][2], bl[4][2];
#pragma unroll
            for (int mi = 0; mi < 4; mi++)
                ldsm4(ah[mi], tAhi + swz64(warp_m * 64 + mi * 16 + lrow, lu));
#pragma unroll
            for (int g = 0; g < 2; g++) {
                uint32_t r[4];
                ldsm4(r, tBhi + swz64(warp_n * 32 + g * 16 + lrow, lu));
                bh[g * 2 + 0][0] = r[0]; bh[g * 2 + 1][0] = r[1];
                bh[g * 2 + 0][1] = r[2]; bh[g * 2 + 1][1] = r[3];
                ldsm4(r, tBlo + swz64(warp_n * 32 + g * 16 + lrow, lu));
                bl[g * 2 + 0][0] = r[0]; bl[g * 2 + 1][0] = r[1];
                bl[g * 2 + 0][1] = r[2]; bl[g * 2 + 1][1] = r[3];
            }
#pragma unroll
            for (int mi = 0; mi < 4; mi++)
#pragma unroll
                for (int ni = 0; ni < 4; ni++) {
                    mma16816h(acc[mi][ni], ah[mi], bh[ni]);
                    mma16816h(acc[mi][ni], ah[mi], bl[ni]);
                }
            uint32_t al[4][4];
#pragma unroll
            for (int mi = 0; mi < 4; mi++)
                ldsm4(al[mi], tAlo + swz64(warp_m * 64 + mi * 16 + lrow, lu));
#pragma unroll
            for (int mi = 0; mi < 4; mi++)
#pragma unroll
                for (int ni = 0; ni < 4; ni++)
                    mma16816h(acc[mi][ni], al[mi], bh[ni]);
        }
    }

    const int quad = lane >> 2;
    const int qt   = lane & 3;
#pragma unroll
    for (int mi = 0; mi < 4; mi++) {
#pragma unroll
        for (int ni = 0; ni < 4; ni++) {
            const int r0 = rowBase + warp_m * 64 + mi * 16 + quad;
            const int r1 = r0 + 8;
            const int cc = colBase + warp_n * 32 + ni * 8 + qt * 2;
            const float* a4 = acc[mi][ni];
            *reinterpret_cast<float2*>(C + (size_t)r0 * Cld + cc) =
                make_float2(a4[0], a4[1]);
            *reinterpret_cast<float2*>(C + (size_t)r1 * Cld + cc) =
                make_float2(a4[2], a4[3]);
        }
    }
}

// ---------------------------------------------------------------------------
// SIM GEMM, symmetric: only tiles with blockIdx.y <= blockIdx.x compute.
// Off-diagonal tiles emit BOTH orientations:
//   direct: P[r][c] = adjmask(r,c) ? e : 0, fused partials
//   mirror: stage unmasked e transposed via smem, then coalesced pass applies
//           adj[c][r], writes P[c][r] + mirror partials.
// ---------------------------------------------------------------------------
__global__ __launch_bounds__(256, 2)
void hmma_sim(const __half* __restrict__ A, __half* __restrict__ P,
              int K, const int* __restrict__ adj, float* __restrict__ part)
{
    if (blockIdx.y > blockIdx.x) return;     // lower triangle handled by mirror

    extern __shared__ char smem[];
    const uint32_t base = smem_u32(smem);

    const int tid  = threadIdx.x;
    const int lane = tid & 31;
    const int wid  = tid >> 5;
    const int warp_m = wid & 1;
    const int warp_n = wid >> 1;
    const int rowBase = blockIdx.y * 128;
    const int colBase = blockIdx.x * 128;
    const bool offdiag = (blockIdx.y != blockIdx.x);

    // L2-prefetch adjacency tiles (direct + mirror)
    {
        const char* ab = reinterpret_cast<const char*>(adj);
#pragma unroll
        for (int i = 0; i < 2; i++) {
            int idx = tid + i * 256;
            int r = idx >> 2, seg = idx & 3;
            asm volatile("prefetch.global.L2 [%0];" ::
                "l"(ab + ((size_t)(rowBase + r) * NN + colBase) * 4 + seg * 128));
            if (offdiag)
                asm volatile("prefetch.global.L2 [%0];" ::
                    "l"(ab + ((size_t)(colBase + r) * NN + rowBase) * 4 + seg * 128));
        }
    }

    float acc[4][4][4];
#pragma unroll
    for (int mi = 0; mi < 4; mi++)
#pragma unroll
        for (int ni = 0; ni < 4; ni++)
#pragma unroll
            for (int r = 0; r < 4; r++) acc[mi][ni][r] = 0.f;

    const int NC = K >> 6;

    auto prefetch = [&](int c, int stage) {
#pragma unroll
        for (int it = 0; it < 8; it++) {
            const int t   = it >> 2;
            const int rem = ((it & 3) << 8) + tid;
            const int row = rem >> 3;
            const int u   = rem & 7;
            const __half* sp = A + (size_t)((t ? colBase : rowBase) + row) * K
                             + ((size_t)c << 6) + u * 8;
            uint32_t dst = base + (uint32_t)stage * 32768u + (uint32_t)t * 16384u
                         + swz128(row, u);
            cpasync16(dst, sp);
        }
        cp_commit();
    };

    prefetch(0, 0);
    prefetch(1, 1);

    for (int c = 0; c < NC; c++) {
        if (c + 1 < NC) asm volatile("cp.async.wait_group 1;" ::: "memory");
        else            asm volatile("cp.async.wait_group 0;" ::: "memory");
        __syncthreads();
        if (c + 2 < NC) prefetch(c + 2, (c + 2) % 3);

        const uint32_t sA = base + (uint32_t)(c % 3) * 32768u;
        const uint32_t sB = sA + 16384u;
        const int lrow = lane & 15;
#pragma unroll
        for (int ks = 0; ks < 4; ks++) {
            const int lu = ks * 2 + (lane >> 4);
            uint32_t ah[4][4], b[4][2];
#pragma unroll
            for (int mi = 0; mi < 4; mi++)
                ldsm4(ah[mi], sA + swz128(warp_m * 64 + mi * 16 + lrow, lu));
#pragma unroll
            for (int g = 0; g < 2; g++) {
                uint32_t t4[4];
                ldsm4(t4, sB + swz128(warp_n * 32 + g * 16 + lrow, lu));
                b[g * 2 + 0][0] = t4[0]; b[g * 2 + 1][0] = t4[1];
                b[g * 2 + 0][1] = t4[2]; b[g * 2 + 1][1] = t4[3];
            }
#pragma unroll
            for (int mi = 0; mi < 4; mi++)
#pragma unroll
                for (int ni = 0; ni < 4; ni++)
                    mma16816h(acc[mi][ni], ah[mi], b[ni]);
        }
    }

    // smem reuse for mirror staging: all warps must be done with ldsm reads
    __syncthreads();
    __half* T = reinterpret_cast<__half*>(smem);   // [128][136] fp16, unmasked e

    // -------- direct epilogue (+ T staging when offdiag) --------
    const int quad = lane >> 2;
    const int qt   = lane & 3;
    const __half HZ = __ushort_as_half((unsigned short)0);
    const int colblock = blockIdx.x * 4 + warp_n;
#pragma unroll
    for (int mi = 0; mi < 4; mi++) {
        const int r0l = warp_m * 64 + mi * 16 + quad;
        const int r1l = r0l + 8;
        const int r0  = rowBase + r0l;
        const int r1  = rowBase + r1l;
        float rs0 = 0.f, rs1 = 0.f;
#pragma unroll
        for (int ni = 0; ni < 4; ni++) {
            const int ccl = warp_n * 32 + ni * 8 + qt * 2;
            const int cc  = colBase + ccl;
            const float* a4 = acc[mi][ni];
            float e00 = __expf(a4[0] - 1.f), e01 = __expf(a4[1] - 1.f);
            float e10 = __expf(a4[2] - 1.f), e11 = __expf(a4[3] - 1.f);
            __half2 eh0 = __floats2half2_rn(e00, e01);
            __half2 eh1 = __floats2half2_rn(e10, e11);
            if (offdiag) {
                T[(ccl + 0) * 136 + r0l] = __low2half(eh0);
                T[(ccl + 1) * 136 + r0l] = __high2half(eh0);
                T[(ccl + 0) * 136 + r1l] = __low2half(eh1);
                T[(ccl + 1) * 136 + r1l] = __high2half(eh1);
            }
            int2 m0 = *reinterpret_cast<const int2*>(adj + (size_t)r0 * NN + cc);
            int2 m1 = *reinterpret_cast<const int2*>(adj + (size_t)r1 * NN + cc);
            __half p00 = (m0.x > 0 || r0 == cc)     ? __low2half(eh0)  : HZ;
            __half p01 = (m0.y > 0 || r0 == cc + 1) ? __high2half(eh0) : HZ;
            __half p10 = (m1.x > 0 || r1 == cc)     ? __low2half(eh1)  : HZ;
            __half p11 = (m1.y > 0 || r1 == cc + 1) ? __high2half(eh1) : HZ;
            __half2 h0 = __halves2half2(p00, p01);
            __half2 h1 = __halves2half2(p10, p11);
            *reinterpret_cast<__half2*>(P + (size_t)r0 * NN + cc) = h0;
            *reinterpret_cast<__half2*>(P + (size_t)r1 * NN + cc) = h1;
            float2 f0 = __half22float2(h0);
            float2 f1 = __half22float2(h1);
            rs0 += f0.x + f0.y;
            rs1 += f1.x + f1.y;
        }
        rs0 += __shfl_xor_sync(0xffffffffu, rs0, 1);
        rs0 += __shfl_xor_sync(0xffffffffu, rs0, 2);
        rs1 += __shfl_xor_sync(0xffffffffu, rs1, 1);
        rs1 += __shfl_xor_sync(0xffffffffu, rs1, 2);
        if (qt == 0) {
            part[(size_t)r0 * 256 + colblock] = rs0;
            part[(size_t)r1 * 256 + colblock] = rs1;
        }
    }

    // -------- mirror pass (coalesced) --------
    if (offdiag) {
        __syncthreads();
        const int c  = tid >> 1;                 // 0..127 (mirror row, local)
        const int rh = (tid & 1) << 6;           // 0 or 64
        const int gc = colBase + c;              // global mirror row
        const int gr = rowBase + rh;             // global mirror col start
        const int* arow = adj + (size_t)gc * NN + gr;
        const __half* Trow = T + c * 136 + rh;
        float s0 = 0.f, s1 = 0.f;
#pragma unroll
        for (int j = 0; j < 64; j += 8) {
            uint4 tv = *reinterpret_cast<const uint4*>(Trow + j);
            int4 ma = *reinterpret_cast<const int4*>(arow + j);
            int4 mb = *reinterpret_cast<const int4*>(arow + j + 4);
            __half2* hv = reinterpret_cast<__half2*>(&tv);
            __half q0 = (ma.x > 0) ? __low2half(hv[0])  : HZ;
            __half q1 = (ma.y > 0) ? __high2half(hv[0]) : HZ;
            __half q2 = (ma.z > 0) ? __low2half(hv[1])  : HZ;
            __half q3 = (ma.w > 0) ? __high2half(hv[1]) : HZ;
            __half q4 = (mb.x > 0) ? __low2half(hv[2])  : HZ;
            __half q5 = (mb.y > 0) ? __high2half(hv[2]) : HZ;
            __half q6 = (mb.z > 0) ? __low2half(hv[3])  : HZ;
            __half q7 = (mb.w > 0) ? __high2half(hv[3]) : HZ;
            hv[0] = __halves2half2(q0, q1);
            hv[1] = __halves2half2(q2, q3);
            hv[2] = __halves2half2(q4, q5);
            hv[3] = __halves2half2(q6, q7);
            *reinterpret_cast<uint4*>(P + (size_t)gc * NN + gr + j) = tv;
            float2 f0 = __half22float2(hv[0]);
            float2 f1 = __half22float2(hv[1]);
            float2 f2 = __half22float2(hv[2]);
            float2 f3 = __half22float2(hv[3]);
            float sj = (f0.x + f0.y) + (f1.x + f1.y)
                     + (f2.x + f2.y) + (f3.x + f3.y);
            if (j < 32) s0 += sj; else s1 += sj;
        }
        const int gbase = blockIdx.y * 4 + (rh >> 5);
        part[(size_t)gc * 256 + gbase]     = s0;
        part[(size_t)gc * 256 + gbase + 1] = s1;
    }
}

// ---------------------------------------------------------------------------
// part_inv: inv[row] = 1 / sum over 256 partials. One warp per row.
// ---------------------------------------------------------------------------
__global__ void part_inv(const float* __restrict__ part, float* __restrict__ inv)
{
    int row  = blockIdx.x * 8 + (threadIdx.x >> 5);
    int lane = threadIdx.x & 31;
    const float4* p4 = reinterpret_cast<const float4*>(part + (size_t)row * 256);
    float s = 0.f;
#pragma unroll
    for (int i = 0; i < 2; i++) {
        float4 v = p4[lane + i * 32];
        s += (v.x + v.y) + (v.z + v.w);
    }
#pragma unroll
    for (int off = 16; off > 0; off >>= 1)
        s += __shfl_xor_sync(0xffffffffu, s, off);
    if (lane == 0) inv[row] = 1.0f / s;
}

// ---------------------------------------------------------------------------
// AV GEMM: out = (P @ V^T) * inv[row]. Single fp16 term, 8 warps,
// CTA 128x128, K-chunk 64, 3-stage pipeline.
// ---------------------------------------------------------------------------
__global__ __launch_bounds__(256, 2)
void hmma_av(const __half* __restrict__ P, const __half* __restrict__ V,
             float* __restrict__ C, int K, int Cld, const float* __restrict__ inv)
{
    extern __shared__ char smem[];
    const uint32_t base = smem_u32(smem);

    const int tid  = threadIdx.x;
    const int lane = tid & 31;
    const int wid  = tid >> 5;
    const int warp_m = wid & 1;
    const int warp_n = wid >> 1;
    const int rowBase = blockIdx.y * 128;
    const int colBase = blockIdx.x * 128;

    float acc[4][4][4];
#pragma unroll
    for (int mi = 0; mi < 4; mi++)
#pragma unroll
        for (int ni = 0; ni < 4; ni++)
#pragma unroll
            for (int r = 0; r < 4; r++) acc[mi][ni][r] = 0.f;

    const int NC = K >> 6;

    auto prefetch = [&](int c, int stage) {
#pragma unroll
        for (int it = 0; it < 8; it++) {
            const int t   = it >> 2;                    // 0 = P, 1 = V
            const int rem = ((it & 3) << 8) + tid;
            const int row = rem >> 3;
            const int u   = rem & 7;
            const __half* sp = (t ? V + (size_t)(colBase + row) * K
                                  : P + (size_t)(rowBase + row) * K)
                             + ((size_t)c << 6) + u * 8;
            uint32_t dst = base + (uint32_t)stage * 32768u + (uint32_t)t * 16384u
                         + swz128(row, u);
            cpasync16(dst, sp);
        }
        cp_commit();
    };

    prefetch(0, 0);
    prefetch(1, 1);

    for (int c = 0; c < NC; c++) {
        if (c + 1 < NC) asm volatile("cp.async.wait_group 1;" ::: "memory");
        else            asm volatile("cp.async.wait_group 0;" ::: "memory");
        __syncthreads();
        if (c + 2 < NC) prefetch(c + 2, (c + 2) % 3);

        const uint32_t sP = base + (uint32_t)(c % 3) * 32768u;
        const uint32_t sV = sP + 16384u;
        const int lrow = lane & 15;
#pragma unroll
        for (int ks = 0; ks < 4; ks++) {
            const int lu = ks * 2 + (lane >> 4);
            uint32_t ap[4][4], b[4][2];
#pragma unroll
            for (int mi = 0; mi < 4; mi++)
                ldsm4(ap[mi], sP + swz128(warp_m * 64 + mi * 16 + lrow, lu));
#pragma unroll
            for (int g = 0; g < 2; g++) {
                uint32_t t4[4];
                ldsm4(t4, sV + swz128(warp_n * 32 + g * 16 + lrow, lu));
                b[g * 2 + 0][0] = t4[0]; b[g * 2 + 1][0] = t4[1];
                b[g * 2 + 0][1] = t4[2]; b[g * 2 + 1][1] = t4[3];
            }
#pragma unroll
            for (int mi = 0; mi < 4; mi++)
#pragma unroll
                for (int ni = 0; ni < 4; ni++)
                    mma16816h(acc[mi][ni], ap[mi], b[ni]);
        }
    }

    const int quad = lane >> 2;
    const int qt   = lane & 3;
#pragma unroll
    for (int mi = 0; mi < 4; mi++) {
        const int r0 = rowBase + warp_m * 64 + mi * 16 + quad;
        const int r1 = r0 + 8;
        const float iv0 = inv[r0];
        const float iv1 = inv[r1];
#pragma unroll
        for (int ni = 0; ni < 4; ni++) {
            const int cc = colBase + warp_n * 32 + ni * 8 + qt * 2;
            const float* a4 = acc[mi][ni];
            *reinterpret_cast<float2*>(C + (size_t)r0 * Cld + cc) =
                make_float2(a4[0] * iv0, a4[1] * iv0);
            *reinterpret_cast<float2*>(C + (size_t)r1 * Cld + cc) =
                make_float2(a4[2] * iv1, a4[3] * iv1);
        }
    }
}

// ---------------------------------------------------------------------------
// prep: per-row normalize Wh -> fp16. One warp per row.
// ---------------------------------------------------------------------------
__global__ void prep_norm_f16(const float* __restrict__ Wh, __half* __restrict__ A)
{
    int row  = blockIdx.x * 8 + (threadIdx.x >> 5);
    int lane = threadIdx.x & 31;
    const float4* r4 = reinterpret_cast<const float4*>(Wh + (size_t)row * DD);

    float4 v[4];
    float ss = 0.f;
#pragma unroll
    for (int i = 0; i < 4; i++) {
        v[i] = r4[lane + i * 32];
        ss = fmaf(v[i].x, v[i].x, ss); ss = fmaf(v[i].y, v[i].y, ss);
        ss = fmaf(v[i].z, v[i].z, ss); ss = fmaf(v[i].w, v[i].w, ss);
    }
#pragma unroll
    for (int off = 16; off > 0; off >>= 1) ss += __shfl_xor_sync(0xffffffffu, ss, off);
    float s = rsqrtf(ss + EPSF);

    __half* pa = A + (size_t)row * DD;
#pragma unroll
    for (int i = 0; i < 4; i++) {
        int col = (lane + i * 32) * 4;
        *reinterpret_cast<__half2*>(pa + col)     = __floats2half2_rn(v[i].x * s, v[i].y * s);
        *reinterpret_cast<__half2*>(pa + col + 2) = __floats2half2_rn(v[i].z * s, v[i].w * s);
    }
}

// ---------------------------------------------------------------------------
// transpose Wh -> fp16 V^T.
// ---------------------------------------------------------------------------
__global__ void t_f16(const float* __restrict__ Wh, __half* __restrict__ th)
{
    __shared__ float t[32][33];
    int bx = blockIdx.x, by = blockIdx.y;
    int tx = threadIdx.x, ty = threadIdx.y;
#pragma unroll
    for (int i = 0; i < 32; i += 8)
        t[ty + i][tx] = Wh[(size_t)(by * 32 + ty + i) * DD + bx * 32 + tx];
    __syncthreads();
#pragma unroll
    for (int i = 0; i < 32; i += 8) {
        size_t o = (size_t)(bx * 32 + ty + i) * NN + by * 32 + tx;
        th[o] = __float2half_rn(t[tx][ty + i]);
    }
}

// ---------------------------------------------------------------------------
extern "C" void kernel_launch(void* const* d_in, const int* in_sizes, int n_in,
                              void* d_out, int out_size)
{
    const float* h   = (const float*)d_in[0];   // [8192, 512]
    const int*   adj = (const int*)d_in[1];     // [8192, 8192]
    const float* W   = (const float*)d_in[2];   // [512, 512]
    float* out = (float*)d_out;                 // [8192, 512]

    void* p;
    cudaGetSymbolAddress(&p, g_Wh);   float*  Wh  = (float*)p;
    cudaGetSymbolAddress(&p, g_hh);   __half* hh  = (__half*)p;
    cudaGetSymbolAddress(&p, g_hl);   __half* hl  = (__half*)p;
    cudaGetSymbolAddress(&p, g_wsh);  __half* wsh = (__half*)p;
    cudaGetSymbolAddress(&p, g_wsl);  __half* wsl = (__half*)p;
    cudaGetSymbolAddress(&p, g_An);   __half* An  = (__half*)p;
    cudaGetSymbolAddress(&p, g_Vt);   __half* Vt  = (__half*)p;
    cudaGetSymbolAddress(&p, g_p);    __half* P   = (__half*)p;
    cudaGetSymbolAddress(&p, g_part); float*  part= (float*)p;
    cudaGetSymbolAddress(&p, g_inv);  float*  inv = (float*)p;

    const int SMEM = 98304;
    cudaFuncSetAttribute((const void*)hmma3h,
                         cudaFuncAttributeMaxDynamicSharedMemorySize, SMEM);
    cudaFuncSetAttribute((const void*)hmma_sim,
                         cudaFuncAttributeMaxDynamicSharedMemorySize, SMEM);
    cudaFuncSetAttribute((const void*)hmma_av,
                         cudaFuncAttributeMaxDynamicSharedMemorySize, SMEM);

    // 1) fp16 splits of h and W
    split_hl<<<(NN * DD + 255) / 256, 256>>>(h, hh, hl, NN * DD);
    split_hl<<<(DD * DD + 255) / 256, 256>>>(W, wsh, wsl, DD * DD);
    // 2) Wh = h @ W^T via 3-term fp16 HMMA (fp32 out)
    hmma3h<<<dim3(DD / 128, NN / 128), 256, SMEM>>>(hh, hl, wsh, wsl, Wh, DD, DD);
    // 3) normalized rows -> fp16
    prep_norm_f16<<<NN / 8, 256>>>(Wh, An);
    // 4) Wh^T -> fp16 (V of AV GEMM)
    t_f16<<<dim3(DD / 32, NN / 32), dim3(32, 8)>>>(Wh, Vt);
    // 5) P = exp(sim - 1) masked + fused partials; symmetric (upper triangle)
    hmma_sim<<<dim3(NN / 128, NN / 128), 256, SMEM>>>(An, P, DD, adj, part);
    // 6) reduce partials -> inv
    part_inv<<<NN / 8, 256>>>(part, inv);
    // 7) out = (P @ V^T) * inv  (single-term fp16 HMMA, K = 8192)
    hmma_av<<<dim3(DD / 128, NN / 128), 256, SMEM>>>(P, Vt, out, NN, DD, inv);
}